// round 13
// baseline (speedup 1.0000x reference)
#include <cuda_runtime.h>
#include <cuda_bf16.h>

// Problem constants (fixed by setup_inputs)
#define B_GRAPHS 2000
#define LGPG 100
#define NPG 20
#define ELPG 10
#define D 300
#define ROWV 75
#define N_LG (B_GRAPHS * LGPG)
#define N_NODES (B_GRAPHS * NPG)
#define E_LAB (B_GRAPHS * ELPG)

// Output layout (flattened tuple, float32)
#define OFF_EDGE 12000000
#define OFF_PTR  12040000
#define OFF_BATCH 12042001

#define N_ITEMS (2 * NPG)          // 40 items per graph
#define GRID_PERSIST (148 * 7)     // one full resident wave

__device__ int g_next;             // global graph-steal counter

__device__ __forceinline__ float4 ldcs4(const float4* p) {
    float4 v;
    asm volatile("ld.global.cs.v4.f32 {%0,%1,%2,%3}, [%4];"
                 : "=f"(v.x), "=f"(v.y), "=f"(v.z), "=f"(v.w) : "l"(p));
    return v;
}
__device__ __forceinline__ void stcs4(float4* p, float4 v) {
    asm volatile("st.global.cs.v4.f32 [%0], {%1,%2,%3,%4};"
                 :: "l"(p), "f"(v.x), "f"(v.y), "f"(v.z), "f"(v.w) : "memory");
}

__global__ void init_kernel() { g_next = 0; }

// Persistent CTAs steal graphs from a global counter (speed-adaptive, no
// fixed-assignment quantization). Per stolen graph: CSR build + local
// item-stealing gather (R7 body, mixed heavy/light order).
__global__ __launch_bounds__(256, 7) void graph_kernel(
    const float* __restrict__ x,                  // [N_LG, D]
    const int* __restrict__ lg_node_idx,          // [N_LG, 2]
    const int* __restrict__ edge_index_labeled,   // [2, E_LAB]
    float* __restrict__ out)
{
    const int tid = threadIdx.x;
    const int lane = tid & 31;

    __shared__ int cur0[NPG], cur1[NPG];
    __shared__ int off0[NPG + 1], off1[NPG + 1];
    __shared__ int list0[LGPG], list1[LGPG];
    __shared__ int idx0[LGPG], idx1[LGPG];
    __shared__ float inv0[NPG], inv1[NPG];
    __shared__ int wctr;
    __shared__ int sg;

    const bool hasB = (lane < 18);

    for (;;) {
        if (tid == 0) sg = atomicAdd(&g_next, 1);
        // barrier: all threads done with previous graph's smem AND see sg
        __syncthreads();
        const int g = sg;
        if (g >= B_GRAPHS) break;

        // ---- setup: CSR contributor lists for graph g ----
        if (tid < NPG) { cur0[tid] = 0; cur1[tid] = 0; }
        if (tid == 128) wctr = 0;
        __syncthreads();

        if (tid < LGPG) {
            int2 p = reinterpret_cast<const int2*>(lg_node_idx)[g * LGPG + tid];
            idx0[tid] = p.x; idx1[tid] = p.y;
            atomicAdd(&cur0[p.x], 1);
            atomicAdd(&cur1[p.y], 1);
        }
        __syncthreads();

        if (tid == 0) {
            int s = 0;
            #pragma unroll
            for (int n = 0; n < NPG; n++) { off0[n] = s; s += cur0[n]; }
            off0[NPG] = s;
        } else if (tid == 32) {
            int s = 0;
            #pragma unroll
            for (int n = 0; n < NPG; n++) { off1[n] = s; s += cur1[n]; }
            off1[NPG] = s;
        }
        __syncthreads();

        if (tid < NPG) {
            int c0 = off0[tid + 1] - off0[tid];
            int c1 = off1[tid + 1] - off1[tid];
            inv0[tid] = c0 > 0 ? 1.0f / (float)c0 : 0.0f;
            inv1[tid] = c1 > 0 ? 1.0f / (float)c1 : 0.0f;
            cur0[tid] = off0[tid];
            cur1[tid] = off1[tid];
        }
        __syncthreads();

        if (tid < LGPG) {
            list0[atomicAdd(&cur0[idx0[tid]], 1)] = tid;
            list1[atomicAdd(&cur1[idx1[tid]], 1)] = tid;
        }
        __syncthreads();

        const float4* xv = reinterpret_cast<const float4*>(x) + (size_t)g * (LGPG * ROWV);
        float4* ov = reinterpret_cast<float4*>(out) + (size_t)g * (NPG * ROWV);

        // ---- local work-stealing gather over 40 items (mixed order) ----
        // item: half = it & 1, n = it >> 1
        for (;;) {
            int it = 0;
            if (lane == 0) it = atomicAdd(&wctr, 1);
            it = __shfl_sync(0xffffffffu, it, 0);
            if (it >= N_ITEMS) break;

            const int half = it & 1;
            const int n = it >> 1;
            float4* onv = ov + n * ROWV;

            if (half == 0) {
                // incoming half: cols [0,50) float4, key idx1. 2 LDGs/iter.
                const int s1 = off1[n], e1 = off1[n + 1];
                const float v1 = inv1[n];
                float4 a0 = make_float4(0.f, 0.f, 0.f, 0.f);
                float4 a1 = make_float4(0.f, 0.f, 0.f, 0.f);
                for (int k = s1; k < e1; k++) {
                    const float4* row = xv + list1[k] * ROWV;
                    float4 t0 = ldcs4(row + lane);
                    float4 t1;
                    if (hasB) t1 = ldcs4(row + lane + 32);
                    a0.x += t0.x; a0.y += t0.y; a0.z += t0.z; a0.w += t0.w;
                    if (hasB) { a1.x += t1.x; a1.y += t1.y; a1.z += t1.z; a1.w += t1.w; }
                }
                a0.x *= v1; a0.y *= v1; a0.z *= v1; a0.w *= v1;
                stcs4(&onv[lane], a0);
                if (hasB) {
                    a1.x *= v1; a1.y *= v1; a1.z *= v1; a1.w *= v1;
                    stcs4(&onv[lane + 32], a1);
                }
            } else if (lane < 25) {
                // outgoing half: cols [50,75) float4, key idx0. Unroll-by-2.
                const int s0 = off0[n], e0 = off0[n + 1];
                const float v0 = inv0[n];
                const int dq = 50 + lane;
                float4 a0 = make_float4(0.f, 0.f, 0.f, 0.f);
                float4 a1 = make_float4(0.f, 0.f, 0.f, 0.f);
                int k = s0;
                for (; k + 1 < e0; k += 2) {
                    float4 t0 = ldcs4(xv + list0[k] * ROWV + dq);
                    float4 t1 = ldcs4(xv + list0[k + 1] * ROWV + dq);
                    a0.x += t0.x; a0.y += t0.y; a0.z += t0.z; a0.w += t0.w;
                    a1.x += t1.x; a1.y += t1.y; a1.z += t1.z; a1.w += t1.w;
                }
                if (k < e0) {
                    float4 t0 = ldcs4(xv + list0[k] * ROWV + dq);
                    a0.x += t0.x; a0.y += t0.y; a0.z += t0.z; a0.w += t0.w;
                }
                float4 r;
                r.x = (a0.x + a1.x) * v0;
                r.y = (a0.y + a1.y) * v0;
                r.z = (a0.z + a1.z) * v0;
                r.w = (a0.w + a1.w) * v0;
                stcs4(&onv[dq], r);
            }
        }

        // ---- aux outputs for graph g ----
        if (tid < 2 * ELPG) {
            int r = tid / ELPG, e = tid % ELPG;
            int gi = r * E_LAB + g * ELPG + e;
            out[OFF_EDGE + gi] = (float)(edge_index_labeled[gi] - g * LGPG);
        } else if (tid >= 64 && tid < 64 + NPG) {
            out[OFF_BATCH + g * NPG + (tid - 64)] = (float)g;
        } else if (tid == 96) {
            out[OFF_PTR + g] = (float)(g * NPG);
            if (g == B_GRAPHS - 1) out[OFF_PTR + B_GRAPHS] = (float)(B_GRAPHS * NPG);
        }
    }
}

extern "C" void kernel_launch(void* const* d_in, const int* in_sizes, int n_in,
                              void* d_out, int out_size) {
    const float* x            = (const float*)d_in[0];
    const int*   lg_node_idx  = (const int*)d_in[1];
    const int*   edge_idx_lab = (const int*)d_in[5];
    float* out = (float*)d_out;

    init_kernel<<<1, 1>>>();
    graph_kernel<<<GRID_PERSIST, 256>>>(x, lg_node_idx, edge_idx_lab, out);
}